// round 1
// baseline (speedup 1.0000x reference)
#include <cuda_runtime.h>
#include <cstdint>
#include <cstddef>

// Sinkhorn: y = exp(x) + eps, then 100x (row-normalize; col-normalize).
// Factored form: y = diag(r) * A * diag(c), A = exp(x)+eps constant.
//   r <- 1/(A c);  c <- 1/(A^T r)
// 16 matrices of 512x512 fp32. One 8-CTA cluster per matrix, A register-resident.

#define N_ITERS 100
#define NDIM 512

__device__ __forceinline__ uint32_t smem_u32(const void* p) {
    return (uint32_t)__cvta_generic_to_shared(p);
}
__device__ __forceinline__ uint32_t mapa_u32(uint32_t addr, uint32_t rank) {
    uint32_t r;
    asm("mapa.shared::cluster.u32 %0, %1, %2;" : "=r"(r) : "r"(addr), "r"(rank));
    return r;
}
__device__ __forceinline__ void st_cluster_v2(uint32_t addr, float a, float b) {
    asm volatile("st.shared::cluster.v2.f32 [%0], {%1, %2};"
                 :: "r"(addr), "f"(a), "f"(b) : "memory");
}
__device__ __forceinline__ void st_cluster_f32(uint32_t addr, float v) {
    asm volatile("st.shared::cluster.f32 [%0], %1;"
                 :: "r"(addr), "f"(v) : "memory");
}
#define CLUSTER_SYNC() do { \
    asm volatile("barrier.cluster.arrive.aligned;" ::: "memory"); \
    asm volatile("barrier.cluster.wait.aligned;"   ::: "memory"); } while (0)

__global__ void __launch_bounds__(256, 1) __cluster_dims__(8, 1, 1)
sinkhorn_kernel(const float* __restrict__ x, float* __restrict__ out)
{
    __shared__ float c_smem[NDIM];        // current column scaling c (full 512)
    __shared__ float part[8][NDIM];       // per-warp column partial sums
    __shared__ float peer_part[8][64];    // incoming per-CTA partials for owned cols

    const int tid  = threadIdx.x;
    const int warp = tid >> 5;
    const int lane = tid & 31;
    const int rank = blockIdx.x & 7;      // CTA rank in cluster = row block
    const int bmat = blockIdx.x >> 3;     // matrix index 0..15

    const int row0 = rank * 64 + warp * 8;     // 8 rows per warp
    // Thread owns cols: col(q) = 32*q + lane, q = 0..15  (strided => conflict-free)

    // ---------------- Prologue: load A = exp(x) + eps into registers ----------
    float a[8][16];
    const float* xbase = x + ((size_t)bmat * NDIM + row0) * NDIM;
    #pragma unroll
    for (int p = 0; p < 8; p++) {
        const float* xrow = xbase + (size_t)p * NDIM + lane;
        #pragma unroll
        for (int q = 0; q < 16; q++) {
            a[p][q] = expf(xrow[32 * q]) + 0.001f;
        }
    }

    // init c = 1
    c_smem[tid] = 1.0f;
    c_smem[tid + 256] = 1.0f;
    __syncthreads();

    const uint32_t peer_base = smem_u32(&peer_part[0][0]);
    const uint32_t c_base    = smem_u32(&c_smem[0]);

    float r[8];

    for (int it = 0; it < N_ITERS; it++) {
        // ---- step 1: row sums  acc_i = (A c)_i ; r = 1/acc  (CTA-local) ----
        float acc[8];
        #pragma unroll
        for (int p = 0; p < 8; p++) acc[p] = 0.0f;
        #pragma unroll
        for (int q = 0; q < 16; q++) {
            float cq = c_smem[32 * q + lane];
            #pragma unroll
            for (int p = 0; p < 8; p++) acc[p] = fmaf(a[p][q], cq, acc[p]);
        }
        #pragma unroll
        for (int off = 16; off > 0; off >>= 1) {
            #pragma unroll
            for (int p = 0; p < 8; p++)
                acc[p] += __shfl_xor_sync(0xffffffffu, acc[p], off);
        }
        #pragma unroll
        for (int p = 0; p < 8; p++) r[p] = 1.0f / acc[p];

        // ---- step 2: column partials  sum_i r_i A_ij  over this warp's 8 rows ----
        #pragma unroll
        for (int q = 0; q < 16; q++) {
            float s = 0.0f;
            #pragma unroll
            for (int p = 0; p < 8; p++) s = fmaf(r[p], a[p][q], s);
            part[warp][32 * q + lane] = s;
        }
        __syncthreads();

        // ---- step 3: intra-CTA reduce (8 warps) + push to owning CTA ----
        {
            int col = 2 * tid;                         // this thread reduces 2 cols
            float s0 = 0.0f, s1 = 0.0f;
            #pragma unroll
            for (int w = 0; w < 8; w++) {
                s0 += part[w][col];
                s1 += part[w][col + 1];
            }
            int owner = col >> 6;                      // CTA owning these columns
            uint32_t dst = mapa_u32(
                peer_base + (uint32_t)((rank * 64 + (col & 63)) * sizeof(float)),
                (uint32_t)owner);
            st_cluster_v2(dst, s0, s1);
        }
        CLUSTER_SYNC();

        // ---- step 4: owner reduces 8 CTA partials, broadcasts c to cluster ----
        if (tid < 64) {
            float s = 0.0f;
            #pragma unroll
            for (int rr = 0; rr < 8; rr++) s += peer_part[rr][tid];
            float cj = 1.0f / s;
            uint32_t off = (uint32_t)((rank * 64 + tid) * sizeof(float));
            #pragma unroll
            for (int rk = 0; rk < 8; rk++)
                st_cluster_f32(mapa_u32(c_base + off, (uint32_t)rk), cj);
        }
        CLUSTER_SYNC();
    }

    // ---------------- Epilogue: y_ij = r_i * A_ij * c_j ----------------
    float cvals[16];
    #pragma unroll
    for (int q = 0; q < 16; q++) cvals[q] = c_smem[32 * q + lane];

    float* obase = out + ((size_t)bmat * NDIM + row0) * NDIM;
    #pragma unroll
    for (int p = 0; p < 8; p++) {
        float* orow = obase + (size_t)p * NDIM + lane;
        #pragma unroll
        for (int q = 0; q < 16; q++) {
            orow[32 * q] = r[p] * a[p][q] * cvals[q];
        }
    }
}

extern "C" void kernel_launch(void* const* d_in, const int* in_sizes, int n_in,
                              void* d_out, int out_size)
{
    (void)in_sizes; (void)n_in; (void)out_size;
    const float* x = (const float*)d_in[0];
    float* out = (float*)d_out;
    // 16 matrices * 8 CTAs = 128 CTAs; __cluster_dims__(8) groups them per matrix.
    sinkhorn_kernel<<<128, 256>>>(x, out);
}